// round 3
// baseline (speedup 1.0000x reference)
#include <cuda_runtime.h>
#include <cuda_bf16.h>

// MyLoss: masked per-class MSE, fused single kernel, software-pipelined loads.
// Output (21 fp32): [0]=loss, [1..10]=loss4each, [11..20]=class_n

#define N_CLASSES 10
#define THREADS   256
#define NBLOCKS   512
#define ITERS     16   // 512*256*16 = 2,097,152 = nvec exactly

__device__ float        g_sum[N_CLASSES];
__device__ float        g_cnt[N_CLASSES];
__device__ unsigned int g_done = 0;

// int (0..9) -> float without I2F: mantissa-trick
__device__ __forceinline__ float small_i2f(int t) {
    return __int_as_float(0x4B000000 + t) - 8388608.0f;
}

__global__ void __launch_bounds__(THREADS, 4)
myloss_fused_kernel(const float4* __restrict__ outv,
                    const int4*   __restrict__ tgtv,
                    const int4*   __restrict__ mskv,
                    int nvec,
                    float* __restrict__ out) {
    // Class-major smem: s[c*THREADS + tid]; lane L always hits bank L%32 ->
    // conflict-free, no atomics in the hot loop.
    __shared__ float s_sum[N_CLASSES * THREADS];
    __shared__ float s_cnt[N_CLASSES * THREADS];
    __shared__ bool  s_is_last;

    const int tid = threadIdx.x;
    #pragma unroll
    for (int c = 0; c < N_CLASSES; ++c)
        s_sum[c * THREADS + tid] = 0.0f;
    __syncthreads();

    // Packed per-thread class counters: 6 bits/class (max 64/thread; we do <=64).
    unsigned int cnt_lo = 0u;   // classes 0..4
    unsigned int cnt_hi = 0u;   // classes 5..9

#define PROC(O, T, M)                                                        \
    do {                                                                     \
        if ((M) == 1) {                                                      \
            float d = (O) - small_i2f(T);                                    \
            s_sum[(T) * THREADS + tid] += d * d;                             \
            if ((T) < 5) cnt_lo += 1u << (6 * (T));                          \
            else         cnt_hi += 1u << (6 * ((T) - 5));                    \
        }                                                                    \
    } while (0)

    const int stride = NBLOCKS * THREADS;
    if (nvec == NBLOCKS * THREADS * ITERS) {
        // Fast path: exact tiling, fully unrolled, prefetch distance 1.
        int i = blockIdx.x * THREADS + tid;
        float4 o0 = __ldcs(&outv[i]);
        int4   t0 = __ldcs(&tgtv[i]);
        int4   m0 = __ldcs(&mskv[i]);
        #pragma unroll
        for (int k = 0; k < ITERS; ++k) {
            float4 o1; int4 t1, m1;
            if (k + 1 < ITERS) {
                int j = i + stride;
                o1 = __ldcs(&outv[j]);
                t1 = __ldcs(&tgtv[j]);
                m1 = __ldcs(&mskv[j]);
            }
            PROC(o0.x, t0.x, m0.x);
            PROC(o0.y, t0.y, m0.y);
            PROC(o0.z, t0.z, m0.z);
            PROC(o0.w, t0.w, m0.w);
            if (k + 1 < ITERS) { o0 = o1; t0 = t1; m0 = m1; i += stride; }
        }
    } else {
        // Generic fallback (any nvec).
        for (int i = blockIdx.x * THREADS + tid; i < nvec; i += stride) {
            float4 o = __ldcs(&outv[i]);
            int4   t = __ldcs(&tgtv[i]);
            int4   m = __ldcs(&mskv[i]);
            PROC(o.x, t.x, m.x);
            PROC(o.y, t.y, m.y);
            PROC(o.z, t.z, m.z);
            PROC(o.w, t.w, m.w);
        }
    }
#undef PROC

    // Unpack packed counters into smem (same conflict-free layout).
    #pragma unroll
    for (int c = 0; c < 5; ++c) {
        s_cnt[c * THREADS + tid]       = (float)((cnt_lo >> (6 * c)) & 63u);
        s_cnt[(c + 5) * THREADS + tid] = (float)((cnt_hi >> (6 * c)) & 63u);
    }
    __syncthreads();

    // Epilogue: 20 reduce-jobs (10 sums + 10 counts) over 8 warps.
    const int wid  = tid >> 5;
    const int lane = tid & 31;
    for (int j = wid; j < 2 * N_CLASSES; j += THREADS / 32) {
        const float* base = (j < N_CLASSES) ? &s_sum[j * THREADS]
                                            : &s_cnt[(j - N_CLASSES) * THREADS];
        float v = 0.0f;
        #pragma unroll
        for (int k = 0; k < THREADS / 32; ++k)
            v += base[k * 32 + lane];
        #pragma unroll
        for (int off = 16; off > 0; off >>= 1)
            v += __shfl_down_sync(0xFFFFFFFFu, v, off);
        if (lane == 0) {
            if (j < N_CLASSES) atomicAdd(&g_sum[j], v);
            else               atomicAdd(&g_cnt[j - N_CLASSES], v);
        }
    }

    // Last-block election.
    if (tid == 0) {
        __threadfence();
        unsigned int ticket = atomicAdd(&g_done, 1u);
        s_is_last = (ticket == gridDim.x - 1);
    }
    __syncthreads();

    if (s_is_last && tid < 32) {
        float l = 0.0f, n = 0.0f;
        if (tid < N_CLASSES) {
            float s = atomicAdd(&g_sum[tid], 0.0f);  // RMW read: latest L2 value
            n       = atomicAdd(&g_cnt[tid], 0.0f);
            l = (n > 0.0f) ? (s / fmaxf(n, 1.0f)) : 0.0f;
            out[1 + tid]             = l;
            out[1 + N_CLASSES + tid] = n;
            g_sum[tid] = 0.0f;                       // reset for next replay
            g_cnt[tid] = 0.0f;
        }
        float w = (tid < N_CLASSES) ? 0.1f * l : 0.0f;
        #pragma unroll
        for (int off = 16; off > 0; off >>= 1)
            w += __shfl_down_sync(0xFFFFFFFFu, w, off);
        if (tid == 0) {
            out[0] = w;
            g_done = 0u;
        }
    }
}

extern "C" void kernel_launch(void* const* d_in, const int* in_sizes, int n_in,
                              void* d_out, int out_size) {
    const float* outputs = (const float*)d_in[0];
    const int*   targets = (const int*)d_in[1];
    const int*   mask    = (const int*)d_in[2];
    float*       out     = (float*)d_out;

    const int n    = in_sizes[0];   // 8,388,608
    const int nvec = n / 4;

    myloss_fused_kernel<<<NBLOCKS, THREADS>>>(
        (const float4*)outputs, (const int4*)targets, (const int4*)mask,
        nvec, out);
}